// round 7
// baseline (speedup 1.0000x reference)
#include <cuda_runtime.h>
#include <math.h>

#define B_ 4
#define T_ 2048
#define C_ 1024
#define H_ 16
#define D_ 64
#define R_ 64
#define M_ (B_*T_)   // 8192

typedef unsigned long long ull;

// Packed f32x2 ops (sm_103a FFMA2 path — PTX-only, per SASS_QUICKREF)
#define FMA_F32X2(d, a, b, c) \
    asm("fma.rn.f32x2 %0, %1, %2, %3;" : "=l"(d) : "l"(a), "l"(b), "l"(c))
#define MUL_F32X2(d, a, b) \
    asm("mul.rn.f32x2 %0, %1, %2;" : "=l"(d) : "l"(a), "l"(b))
#define PACK_DUP_F32X2(d, s) \
    asm("mov.b64 %0, {%1, %1};" : "=l"(d) : "r"(__float_as_uint(s)))
#define UNPACK_F32X2(lo, hi, in) \
    { unsigned _l, _h; asm("mov.b64 {%0, %1}, %2;" : "=r"(_l), "=r"(_h) : "l"(in)); \
      lo = __uint_as_float(_l); hi = __uint_as_float(_h); }

// Scratch (device globals: allocation-free per harness rules)
__device__ float g_xv [3 * M_ * R_];   //  6 MB
__device__ float g_qkv[3 * M_ * C_];   // 96 MB
__device__ float g_y  [M_ * C_];       // 32 MB
__device__ float g_yv [M_ * R_];       //  2 MB

// ---------------------------------------------------------------------------
// proj_rank: out[m,r] = s_r * sum_c A[m,c] * V[r,c]
// ---------------------------------------------------------------------------
__global__ __launch_bounds__(256) void proj_rank_kernel(
    const float* __restrict__ A,
    const float* __restrict__ V0, const float* __restrict__ V1,
    const float* __restrict__ V2,
    float* __restrict__ Out)
{
    const int proj = blockIdx.y;
    const float* V = (proj == 0) ? V0 : (proj == 1) ? V1 : V2;
    float* out = Out + (size_t)proj * (M_ * R_);
    const int m0 = blockIdx.x * 64;

    __shared__ float As[64][33];
    __shared__ float Bs[64][33];

    const int tid = threadIdx.x;
    const int ty = tid >> 4, tx = tid & 15;

    float acc[4][4] = {};

    for (int k0 = 0; k0 < C_; k0 += 32) {
        #pragma unroll
        for (int l = 0; l < 2; l++) {
            int idx = tid + l * 256;
            int row = idx >> 3;
            int kc  = (idx & 7) << 2;
            float4 a = *(const float4*)(A + (size_t)(m0 + row) * C_ + k0 + kc);
            As[row][kc+0] = a.x; As[row][kc+1] = a.y;
            As[row][kc+2] = a.z; As[row][kc+3] = a.w;
            float4 b = *(const float4*)(V + (size_t)row * C_ + k0 + kc);
            Bs[row][kc+0] = b.x; Bs[row][kc+1] = b.y;
            Bs[row][kc+2] = b.z; Bs[row][kc+3] = b.w;
        }
        __syncthreads();
        #pragma unroll
        for (int k = 0; k < 32; k++) {
            float a[4], bb[4];
            #pragma unroll
            for (int i = 0; i < 4; i++) a[i] = As[ty*4+i][k];
            #pragma unroll
            for (int j = 0; j < 4; j++) bb[j] = Bs[tx*4+j][k];
            #pragma unroll
            for (int i = 0; i < 4; i++)
                #pragma unroll
                for (int j = 0; j < 4; j++)
                    acc[i][j] = fmaf(a[i], bb[j], acc[i][j]);
        }
        __syncthreads();
    }

    float sdec[4];
    #pragma unroll
    for (int j = 0; j < 4; j++)
        sdec[j] = powf((float)(tx*4 + j + 1), -0.7f);

    #pragma unroll
    for (int i = 0; i < 4; i++)
        #pragma unroll
        for (int j = 0; j < 4; j++)
            out[(size_t)(m0 + ty*4 + i) * R_ + tx*4 + j] = acc[i][j] * sdec[j];
}

// ---------------------------------------------------------------------------
// rank_expand: out[m,n] = sum_{k<64} A[m*64+k] * U[n*64+k]
// ---------------------------------------------------------------------------
__global__ __launch_bounds__(256) void rank_expand_kernel(
    const float* __restrict__ A, const float* __restrict__ U,
    float* __restrict__ out)
{
    const int m0 = blockIdx.x * 64, n0 = blockIdx.y * 64;
    __shared__ float As[64][65];
    __shared__ float Bs[64][65];
    const int tid = threadIdx.x;
    const int ty = tid >> 4, tx = tid & 15;

    #pragma unroll
    for (int l = 0; l < 4; l++) {
        int idx = tid + l * 256;
        int row = idx >> 4;
        int kc  = (idx & 15) << 2;
        float4 a = *(const float4*)(A + (size_t)(m0 + row) * R_ + kc);
        As[row][kc+0] = a.x; As[row][kc+1] = a.y;
        As[row][kc+2] = a.z; As[row][kc+3] = a.w;
        float4 b = *(const float4*)(U + (size_t)(n0 + row) * R_ + kc);
        Bs[row][kc+0] = b.x; Bs[row][kc+1] = b.y;
        Bs[row][kc+2] = b.z; Bs[row][kc+3] = b.w;
    }
    __syncthreads();

    float acc[4][4] = {};
    #pragma unroll
    for (int k = 0; k < 64; k++) {
        float a[4], bb[4];
        #pragma unroll
        for (int i = 0; i < 4; i++) a[i] = As[ty*4+i][k];
        #pragma unroll
        for (int j = 0; j < 4; j++) bb[j] = Bs[tx*4+j][k];
        #pragma unroll
        for (int i = 0; i < 4; i++)
            #pragma unroll
            for (int j = 0; j < 4; j++)
                acc[i][j] = fmaf(a[i], bb[j], acc[i][j]);
    }

    #pragma unroll
    for (int i = 0; i < 4; i++)
        #pragma unroll
        for (int j = 0; j < 4; j++)
            out[(size_t)(m0 + ty*4 + i) * C_ + n0 + tx*4 + j] = acc[i][j];
}

// ---------------------------------------------------------------------------
// Flash attention (fp32, FFMA2-packed): one CTA per (q-tile 64, head, batch).
// K stored TRANSPOSED in shared (Kt[d][row], pitch 66) so the micro-tile's
// j-pairs load as one LDS.64 and accumulate via fma.rn.f32x2 (FFMA2).
// ---------------------------------------------------------------------------
#define QP 65
#define KTP 66
#define VP 66
#define PP 65
#define ATTN_SMEM ((64*QP + 64*KTP + 64*VP + 64*PP) * (int)sizeof(float))

__global__ __launch_bounds__(256, 2) void attn_kernel(
    const float* __restrict__ q, const float* __restrict__ k,
    const float* __restrict__ v, float* __restrict__ y)
{
    extern __shared__ float sm[];
    float* Qs = sm;                     // [64][QP]   row-major
    float* Kt = sm + 64*QP;             // [64][KTP]  TRANSPOSED: Kt[d][row]
    float* Vs = sm + 64*QP + 64*KTP;    // [64][VP]   row-major
    float* Ps = Vs + 64*VP;             // [64][PP]

    const int qt = gridDim.x - 1 - blockIdx.x;   // heavy CTAs first
    const int h  = blockIdx.y, b = blockIdx.z;
    const size_t base = (size_t)b * T_ * C_ + h * 64;

    const int tid = threadIdx.x;
    const int ty = tid >> 4, tx = tid & 15;

    // Load Q tile, folding in softmax scale 1/sqrt(64) = 0.125
    #pragma unroll
    for (int l = 0; l < 4; l++) {
        int idx = tid + l * 256;
        int row = idx >> 4;
        int dc  = (idx & 15) << 2;
        float4 a = *(const float4*)(q + base + (size_t)(qt*64 + row) * C_ + dc);
        Qs[row*QP + dc+0] = a.x * 0.125f;
        Qs[row*QP + dc+1] = a.y * 0.125f;
        Qs[row*QP + dc+2] = a.z * 0.125f;
        Qs[row*QP + dc+3] = a.w * 0.125f;
    }

    float m_i[4], l_i[4];
    ull oacc[4][2];                     // packed f32x2 output accumulators
    #pragma unroll
    for (int i = 0; i < 4; i++) {
        m_i[i] = -1e30f; l_i[i] = 0.0f;
        oacc[i][0] = 0ull; oacc[i][1] = 0ull;
    }

    for (int jt = 0; jt <= qt; jt++) {
        // Load K (transposed into Kt) and V tiles
        #pragma unroll
        for (int l = 0; l < 4; l++) {
            int idx = tid + l * 256;
            int row = idx >> 4;
            int dc  = (idx & 15) << 2;
            size_t g = base + (size_t)(jt*64 + row) * C_ + dc;
            float4 a = *(const float4*)(k + g);
            Kt[(dc+0)*KTP + row] = a.x;
            Kt[(dc+1)*KTP + row] = a.y;
            Kt[(dc+2)*KTP + row] = a.z;
            Kt[(dc+3)*KTP + row] = a.w;
            float4 bb = *(const float4*)(v + g);
            Vs[row*VP + dc+0] = bb.x; Vs[row*VP + dc+1] = bb.y;
            Vs[row*VP + dc+2] = bb.z; Vs[row*VP + dc+3] = bb.w;
        }
        __syncthreads();

        // S = Q K^T via FFMA2: j-pairs from Kt row (LDS.64), Q scalar dup
        ull sacc[4][2] = {{0ull,0ull},{0ull,0ull},{0ull,0ull},{0ull,0ull}};
        #pragma unroll 8
        for (int d = 0; d < 64; d++) {
            ull kp0 = *(const ull*)(Kt + d*KTP + tx*4);
            ull kp1 = *(const ull*)(Kt + d*KTP + tx*4 + 2);
            #pragma unroll
            for (int i = 0; i < 4; i++) {
                float aq = Qs[(ty*4+i)*QP + d];
                ull ad; PACK_DUP_F32X2(ad, aq);
                FMA_F32X2(sacc[i][0], ad, kp0, sacc[i][0]);
                FMA_F32X2(sacc[i][1], ad, kp1, sacc[i][1]);
            }
        }

        // Unpack S
        float s[4][4];
        #pragma unroll
        for (int i = 0; i < 4; i++) {
            UNPACK_F32X2(s[i][0], s[i][1], sacc[i][0]);
            UNPACK_F32X2(s[i][2], s[i][3], sacc[i][1]);
        }

        if (jt == qt) {   // causal mask on the diagonal tile
            #pragma unroll
            for (int i = 0; i < 4; i++)
                #pragma unroll
                for (int j = 0; j < 4; j++)
                    if (tx*4 + j > ty*4 + i) s[i][j] = -1e30f;
        }

        // Online softmax per Q row (row group = 16 tx lanes)
        #pragma unroll
        for (int i = 0; i < 4; i++) {
            float mx = fmaxf(fmaxf(s[i][0], s[i][1]), fmaxf(s[i][2], s[i][3]));
            #pragma unroll
            for (int off = 8; off >= 1; off >>= 1)
                mx = fmaxf(mx, __shfl_xor_sync(0xffffffffu, mx, off));
            float mnew = fmaxf(m_i[i], mx);
            float corr = __expf(m_i[i] - mnew);
            float rs = 0.0f;
            #pragma unroll
            for (int j = 0; j < 4; j++) {
                float p = __expf(s[i][j] - mnew);
                s[i][j] = p;
                rs += p;
            }
            #pragma unroll
            for (int off = 8; off >= 1; off >>= 1)
                rs += __shfl_xor_sync(0xffffffffu, rs, off);
            l_i[i] = l_i[i] * corr + rs;
            m_i[i] = mnew;
            ull cd; PACK_DUP_F32X2(cd, corr);
            MUL_F32X2(oacc[i][0], oacc[i][0], cd);
            MUL_F32X2(oacc[i][1], oacc[i][1], cd);
            #pragma unroll
            for (int j = 0; j < 4; j++)
                Ps[(ty*4+i)*PP + tx*4 + j] = s[i][j];
        }
        __syncthreads();

        // O += P V via FFMA2: j-pairs from Vs row (LDS.64), P scalar dup
        #pragma unroll 8
        for (int kv = 0; kv < 64; kv++) {
            ull vp0 = *(const ull*)(Vs + kv*VP + tx*4);
            ull vp1 = *(const ull*)(Vs + kv*VP + tx*4 + 2);
            #pragma unroll
            for (int i = 0; i < 4; i++) {
                float pv = Ps[(ty*4+i)*PP + kv];
                ull pd; PACK_DUP_F32X2(pd, pv);
                FMA_F32X2(oacc[i][0], pd, vp0, oacc[i][0]);
                FMA_F32X2(oacc[i][1], pd, vp1, oacc[i][1]);
            }
        }
        __syncthreads();   // protect Kt/Vs/Ps before next tile load
    }

    // Epilogue: normalize and store
    #pragma unroll
    for (int i = 0; i < 4; i++) {
        float inv = 1.0f / l_i[i];
        float o0, o1, o2, o3;
        UNPACK_F32X2(o0, o1, oacc[i][0]);
        UNPACK_F32X2(o2, o3, oacc[i][1]);
        float* dst = y + base + (size_t)(qt*64 + ty*4 + i) * C_ + tx*4;
        dst[0] = o0 * inv; dst[1] = o1 * inv;
        dst[2] = o2 * inv; dst[3] = o3 * inv;
    }
}

// ---------------------------------------------------------------------------
extern "C" void kernel_launch(void* const* d_in, const int* in_sizes, int n_in,
                              void* d_out, int out_size)
{
    const float* x  = (const float*)d_in[0];
    const float* qU = (const float*)d_in[1];
    const float* qV = (const float*)d_in[2];
    const float* kU = (const float*)d_in[3];
    const float* kV = (const float*)d_in[4];
    const float* vU = (const float*)d_in[5];
    const float* vV = (const float*)d_in[6];
    const float* cU = (const float*)d_in[7];
    const float* cV = (const float*)d_in[8];
    float* out = (float*)d_out;

    float *xv, *qkv, *y, *yv;
    cudaGetSymbolAddress((void**)&xv,  g_xv);
    cudaGetSymbolAddress((void**)&qkv, g_qkv);
    cudaGetSymbolAddress((void**)&y,   g_y);
    cudaGetSymbolAddress((void**)&yv,  g_yv);

    cudaFuncSetAttribute(attn_kernel,
                         cudaFuncAttributeMaxDynamicSharedMemorySize, ATTN_SMEM);

    // 1) xv_{q,k,v} = (x @ V^T) * s
    proj_rank_kernel<<<dim3(M_/64, 3), 256>>>(x, qV, kV, vV, xv);

    // 2) q,k,v = xv @ U^T
    rank_expand_kernel<<<dim3(M_/64, C_/64), 256>>>(xv,             qU, qkv);
    rank_expand_kernel<<<dim3(M_/64, C_/64), 256>>>(xv +   M_*R_,   kU, qkv + (size_t)M_*C_);
    rank_expand_kernel<<<dim3(M_/64, C_/64), 256>>>(xv + 2*M_*R_,   vU, qkv + 2*(size_t)M_*C_);

    // 3) y = causal softmax attention
    attn_kernel<<<dim3(T_/64, H_, B_), 256, ATTN_SMEM>>>(
        qkv, qkv + (size_t)M_*C_, qkv + 2*(size_t)M_*C_, y);

    // 4) yv = (y @ cV^T) * s ;  5) out = yv @ cU^T
    proj_rank_kernel<<<dim3(M_/64, 1), 256>>>(y, cV, cV, cV, yv);
    rank_expand_kernel<<<dim3(M_/64, C_/64), 256>>>(yv, cU, out);
}

// round 10
// speedup vs baseline: 2.1372x; 2.1372x over previous
#include <cuda_runtime.h>
#include <math.h>

#define B_ 4
#define T_ 2048
#define C_ 1024
#define H_ 16
#define D_ 64
#define R_ 64
#define M_ (B_*T_)   // 8192

typedef unsigned long long ull;

// Scratch (device globals: allocation-free per harness rules)
__device__ float g_xv [3 * M_ * R_];   //  6 MB
__device__ float g_qkv[3 * M_ * C_];   // 96 MB
__device__ float g_y  [M_ * C_];       // 32 MB
__device__ float g_yv [M_ * R_];       //  2 MB

// ---------------------------------------------------------------------------
// tf32 mma.sync helpers
// ---------------------------------------------------------------------------
__device__ __forceinline__ unsigned f2tf32(float x) {
    unsigned r; asm("cvt.rna.tf32.f32 %0, %1;" : "=r"(r) : "f"(x)); return r;
}
__device__ __forceinline__ void mma_tf32(float* d,
    unsigned a0, unsigned a1, unsigned a2, unsigned a3,
    unsigned b0, unsigned b1)
{
    asm volatile(
        "mma.sync.aligned.m16n8k8.row.col.f32.tf32.tf32.f32 "
        "{%0,%1,%2,%3}, {%4,%5,%6,%7}, {%8,%9}, {%0,%1,%2,%3};"
        : "+f"(d[0]), "+f"(d[1]), "+f"(d[2]), "+f"(d[3])
        : "r"(a0), "r"(a1), "r"(a2), "r"(a3), "r"(b0), "r"(b1));
}

// ---------------------------------------------------------------------------
// proj_rank: out[m,r] = s_r * sum_c A[m,c] * V[r,c]
// ---------------------------------------------------------------------------
__global__ __launch_bounds__(256) void proj_rank_kernel(
    const float* __restrict__ A,
    const float* __restrict__ V0, const float* __restrict__ V1,
    const float* __restrict__ V2,
    float* __restrict__ Out)
{
    const int proj = blockIdx.y;
    const float* V = (proj == 0) ? V0 : (proj == 1) ? V1 : V2;
    float* out = Out + (size_t)proj * (M_ * R_);
    const int m0 = blockIdx.x * 64;

    __shared__ float As[64][33];
    __shared__ float Bs[64][33];

    const int tid = threadIdx.x;
    const int ty = tid >> 4, tx = tid & 15;

    float acc[4][4] = {};

    for (int k0 = 0; k0 < C_; k0 += 32) {
        #pragma unroll
        for (int l = 0; l < 2; l++) {
            int idx = tid + l * 256;
            int row = idx >> 3;
            int kc  = (idx & 7) << 2;
            float4 a = *(const float4*)(A + (size_t)(m0 + row) * C_ + k0 + kc);
            As[row][kc+0] = a.x; As[row][kc+1] = a.y;
            As[row][kc+2] = a.z; As[row][kc+3] = a.w;
            float4 b = *(const float4*)(V + (size_t)row * C_ + k0 + kc);
            Bs[row][kc+0] = b.x; Bs[row][kc+1] = b.y;
            Bs[row][kc+2] = b.z; Bs[row][kc+3] = b.w;
        }
        __syncthreads();
        #pragma unroll
        for (int k = 0; k < 32; k++) {
            float a[4], bb[4];
            #pragma unroll
            for (int i = 0; i < 4; i++) a[i] = As[ty*4+i][k];
            #pragma unroll
            for (int j = 0; j < 4; j++) bb[j] = Bs[tx*4+j][k];
            #pragma unroll
            for (int i = 0; i < 4; i++)
                #pragma unroll
                for (int j = 0; j < 4; j++)
                    acc[i][j] = fmaf(a[i], bb[j], acc[i][j]);
        }
        __syncthreads();
    }

    float sdec[4];
    #pragma unroll
    for (int j = 0; j < 4; j++)
        sdec[j] = powf((float)(tx*4 + j + 1), -0.7f);

    #pragma unroll
    for (int i = 0; i < 4; i++)
        #pragma unroll
        for (int j = 0; j < 4; j++)
            out[(size_t)(m0 + ty*4 + i) * R_ + tx*4 + j] = acc[i][j] * sdec[j];
}

// ---------------------------------------------------------------------------
// rank_expand: out[m,n] = sum_{k<64} A[m*64+k] * U[n*64+k]
// ---------------------------------------------------------------------------
__global__ __launch_bounds__(256) void rank_expand_kernel(
    const float* __restrict__ A, const float* __restrict__ U,
    float* __restrict__ out)
{
    const int m0 = blockIdx.x * 64, n0 = blockIdx.y * 64;
    __shared__ float As[64][65];
    __shared__ float Bs[64][65];
    const int tid = threadIdx.x;
    const int ty = tid >> 4, tx = tid & 15;

    #pragma unroll
    for (int l = 0; l < 4; l++) {
        int idx = tid + l * 256;
        int row = idx >> 4;
        int kc  = (idx & 15) << 2;
        float4 a = *(const float4*)(A + (size_t)(m0 + row) * R_ + kc);
        As[row][kc+0] = a.x; As[row][kc+1] = a.y;
        As[row][kc+2] = a.z; As[row][kc+3] = a.w;
        float4 b = *(const float4*)(U + (size_t)(n0 + row) * R_ + kc);
        Bs[row][kc+0] = b.x; Bs[row][kc+1] = b.y;
        Bs[row][kc+2] = b.z; Bs[row][kc+3] = b.w;
    }
    __syncthreads();

    float acc[4][4] = {};
    #pragma unroll
    for (int k = 0; k < 64; k++) {
        float a[4], bb[4];
        #pragma unroll
        for (int i = 0; i < 4; i++) a[i] = As[ty*4+i][k];
        #pragma unroll
        for (int j = 0; j < 4; j++) bb[j] = Bs[tx*4+j][k];
        #pragma unroll
        for (int i = 0; i < 4; i++)
            #pragma unroll
            for (int j = 0; j < 4; j++)
                acc[i][j] = fmaf(a[i], bb[j], acc[i][j]);
    }

    #pragma unroll
    for (int i = 0; i < 4; i++)
        #pragma unroll
        for (int j = 0; j < 4; j++)
            out[(size_t)(m0 + ty*4 + i) * C_ + n0 + tx*4 + j] = acc[i][j];
}

// ---------------------------------------------------------------------------
// Flash attention via tf32 mma.sync (m16n8k8).
// CTA tile: 128 q-rows x 64 kv; 8 warps, each warp owns 16 q-rows (m16),
// 8 n-tiles of 8 across the 64 kv cols, K-loop in 8 steps of 8.
// Shared layouts (conflict-free fragment access):
//   Qs [128][68] tf32   A-frags: addr (4g+t)%32 distinct
//   Kt [64d][72] tf32   B-frags: addr (8t+g)%32 distinct (K transposed)
//   Vs [64kv][72] tf32  B-frags: conflict-free as above
//   Ps [128][68] tf32   P staging between QK-softmax and PV
// ---------------------------------------------------------------------------
#define QPITCH 68
#define KPITCH 72
#define VPITCH 72
#define PPITCH 68
#define ATTN_SMEM ((128*QPITCH + 64*KPITCH + 64*VPITCH + 128*PPITCH) * 4)

__global__ __launch_bounds__(256, 2) void attn_mma_kernel(
    const float* __restrict__ q, const float* __restrict__ k,
    const float* __restrict__ v, float* __restrict__ y)
{
    extern __shared__ unsigned su[];
    unsigned* Qs = su;                       // [128][QPITCH]
    unsigned* Kt = su + 128*QPITCH;          // [64 d][KPITCH]
    unsigned* Vs = Kt + 64*KPITCH;           // [64 kv][VPITCH]
    unsigned* Ps = Vs + 64*VPITCH;           // [128][PPITCH]

    const int qt = (int)gridDim.x - 1 - (int)blockIdx.x;  // heavy CTAs first
    const int h  = blockIdx.y, b = blockIdx.z;
    const size_t base = (size_t)b * T_ * C_ + h * 64;

    const int tid  = threadIdx.x;
    const int w    = tid >> 5;
    const int lane = tid & 31;
    const int g    = lane >> 2, t = lane & 3;

    // --- Load Q (128x64), fold softmax scale 0.125, convert to tf32 ---
    #pragma unroll
    for (int l = 0; l < 8; l++) {
        int idx = tid + l * 256;
        int row = idx >> 4, dc = (idx & 15) << 2;
        float4 a = *(const float4*)(q + base + (size_t)(qt*128 + row) * C_ + dc);
        Qs[row*QPITCH + dc+0] = f2tf32(a.x * 0.125f);
        Qs[row*QPITCH + dc+1] = f2tf32(a.y * 0.125f);
        Qs[row*QPITCH + dc+2] = f2tf32(a.z * 0.125f);
        Qs[row*QPITCH + dc+3] = f2tf32(a.w * 0.125f);
    }

    float oacc[8][4];
    #pragma unroll
    for (int nt = 0; nt < 8; nt++)
        #pragma unroll
        for (int r = 0; r < 4; r++) oacc[nt][r] = 0.0f;
    float m0 = -1e30f, m1 = -1e30f, l0 = 0.0f, l1 = 0.0f;

    const int num_j = 2 * (qt + 1);
    for (int j = 0; j < num_j; j++) {
        // K: scattered-row gmem read -> conflict-free transposed STS into Kt
        #pragma unroll
        for (int l = 0; l < 4; l++) {
            int idx = tid + l * 256;
            int row = idx & 63, dc = (idx >> 6) << 2;
            float4 a = *(const float4*)(k + base + (size_t)(j*64 + row) * C_ + dc);
            Kt[(dc+0)*KPITCH + row] = f2tf32(a.x);
            Kt[(dc+1)*KPITCH + row] = f2tf32(a.y);
            Kt[(dc+2)*KPITCH + row] = f2tf32(a.z);
            Kt[(dc+3)*KPITCH + row] = f2tf32(a.w);
        }
        // V: coalesced, row-major
        #pragma unroll
        for (int l = 0; l < 4; l++) {
            int idx = tid + l * 256;
            int row = idx >> 4, dc = (idx & 15) << 2;
            float4 a = *(const float4*)(v + base + (size_t)(j*64 + row) * C_ + dc);
            Vs[row*VPITCH + dc+0] = f2tf32(a.x);
            Vs[row*VPITCH + dc+1] = f2tf32(a.y);
            Vs[row*VPITCH + dc+2] = f2tf32(a.z);
            Vs[row*VPITCH + dc+3] = f2tf32(a.w);
        }
        __syncthreads();

        // --- S = Q K^T ---
        float sacc[8][4];
        #pragma unroll
        for (int nt = 0; nt < 8; nt++)
            #pragma unroll
            for (int r = 0; r < 4; r++) sacc[nt][r] = 0.0f;

        #pragma unroll
        for (int kk = 0; kk < 8; kk++) {
            unsigned a0 = Qs[(w*16+g  )*QPITCH + kk*8 + t    ];
            unsigned a1 = Qs[(w*16+g+8)*QPITCH + kk*8 + t    ];
            unsigned a2 = Qs[(w*16+g  )*QPITCH + kk*8 + t + 4];
            unsigned a3 = Qs[(w*16+g+8)*QPITCH + kk*8 + t + 4];
            #pragma unroll
            for (int nt = 0; nt < 8; nt++) {
                unsigned b0 = Kt[(kk*8+t  )*KPITCH + nt*8 + g];
                unsigned b1 = Kt[(kk*8+t+4)*KPITCH + nt*8 + g];
                mma_tf32(sacc[nt], a0, a1, a2, a3, b0, b1);
            }
        }

        // causal mask (only the two diagonal-straddling KV tiles need it)
        if (j >= 2*qt) {
            int qr0 = qt*128 + w*16 + g, qr1 = qr0 + 8;
            #pragma unroll
            for (int nt = 0; nt < 8; nt++) {
                int kc0 = j*64 + nt*8 + 2*t, kc1 = kc0 + 1;
                if (kc0 > qr0) sacc[nt][0] = -1e30f;
                if (kc1 > qr0) sacc[nt][1] = -1e30f;
                if (kc0 > qr1) sacc[nt][2] = -1e30f;
                if (kc1 > qr1) sacc[nt][3] = -1e30f;
            }
        }

        // --- online softmax: rows r0=(w*16+g), r1=r0+8, quad-replicated ---
        float mx0 = -1e30f, mx1 = -1e30f;
        #pragma unroll
        for (int nt = 0; nt < 8; nt++) {
            mx0 = fmaxf(mx0, fmaxf(sacc[nt][0], sacc[nt][1]));
            mx1 = fmaxf(mx1, fmaxf(sacc[nt][2], sacc[nt][3]));
        }
        mx0 = fmaxf(mx0, __shfl_xor_sync(0xffffffffu, mx0, 1));
        mx0 = fmaxf(mx0, __shfl_xor_sync(0xffffffffu, mx0, 2));
        mx1 = fmaxf(mx1, __shfl_xor_sync(0xffffffffu, mx1, 1));
        mx1 = fmaxf(mx1, __shfl_xor_sync(0xffffffffu, mx1, 2));

        float mn0 = fmaxf(m0, mx0), mn1 = fmaxf(m1, mx1);
        float c0 = __expf(m0 - mn0), c1 = __expf(m1 - mn1);
        float sum0 = 0.0f, sum1 = 0.0f;

        #pragma unroll
        for (int nt = 0; nt < 8; nt++) {
            float p00 = __expf(sacc[nt][0] - mn0);
            float p01 = __expf(sacc[nt][1] - mn0);
            float p10 = __expf(sacc[nt][2] - mn1);
            float p11 = __expf(sacc[nt][3] - mn1);
            sum0 += p00 + p01;
            sum1 += p10 + p11;
            ull pk0 = (ull)f2tf32(p00) | ((ull)f2tf32(p01) << 32);
            ull pk1 = (ull)f2tf32(p10) | ((ull)f2tf32(p11) << 32);
            *(ull*)(Ps + (w*16+g  )*PPITCH + nt*8 + 2*t) = pk0;
            *(ull*)(Ps + (w*16+g+8)*PPITCH + nt*8 + 2*t) = pk1;
        }
        sum0 += __shfl_xor_sync(0xffffffffu, sum0, 1);
        sum0 += __shfl_xor_sync(0xffffffffu, sum0, 2);
        sum1 += __shfl_xor_sync(0xffffffffu, sum1, 1);
        sum1 += __shfl_xor_sync(0xffffffffu, sum1, 2);

        l0 = l0 * c0 + sum0;  m0 = mn0;
        l1 = l1 * c1 + sum1;  m1 = mn1;
        #pragma unroll
        for (int nt = 0; nt < 8; nt++) {
            oacc[nt][0] *= c0; oacc[nt][1] *= c0;
            oacc[nt][2] *= c1; oacc[nt][3] *= c1;
        }
        __syncthreads();

        // --- O += P V ---
        #pragma unroll
        for (int kk = 0; kk < 8; kk++) {
            unsigned a0 = Ps[(w*16+g  )*PPITCH + kk*8 + t    ];
            unsigned a1 = Ps[(w*16+g+8)*PPITCH + kk*8 + t    ];
            unsigned a2 = Ps[(w*16+g  )*PPITCH + kk*8 + t + 4];
            unsigned a3 = Ps[(w*16+g+8)*PPITCH + kk*8 + t + 4];
            #pragma unroll
            for (int nt = 0; nt < 8; nt++) {
                unsigned b0 = Vs[(kk*8+t  )*VPITCH + nt*8 + g];
                unsigned b1 = Vs[(kk*8+t+4)*VPITCH + nt*8 + g];
                mma_tf32(oacc[nt], a0, a1, a2, a3, b0, b1);
            }
        }
        __syncthreads();   // protect Kt/Vs/Ps before next tile load
    }

    // --- epilogue: normalize, store ---
    float i0 = 1.0f / l0, i1 = 1.0f / l1;
    int r0 = qt*128 + w*16 + g;
    #pragma unroll
    for (int nt = 0; nt < 8; nt++) {
        float2 s0 = make_float2(oacc[nt][0] * i0, oacc[nt][1] * i0);
        float2 s1 = make_float2(oacc[nt][2] * i1, oacc[nt][3] * i1);
        *(float2*)(y + base + (size_t)r0     * C_ + nt*8 + 2*t) = s0;
        *(float2*)(y + base + (size_t)(r0+8) * C_ + nt*8 + 2*t) = s1;
    }
}

// ---------------------------------------------------------------------------
extern "C" void kernel_launch(void* const* d_in, const int* in_sizes, int n_in,
                              void* d_out, int out_size)
{
    const float* x  = (const float*)d_in[0];
    const float* qU = (const float*)d_in[1];
    const float* qV = (const float*)d_in[2];
    const float* kU = (const float*)d_in[3];
    const float* kV = (const float*)d_in[4];
    const float* vU = (const float*)d_in[5];
    const float* vV = (const float*)d_in[6];
    const float* cU = (const float*)d_in[7];
    const float* cV = (const float*)d_in[8];
    float* out = (float*)d_out;

    float *xv, *qkv, *y, *yv;
    cudaGetSymbolAddress((void**)&xv,  g_xv);
    cudaGetSymbolAddress((void**)&qkv, g_qkv);
    cudaGetSymbolAddress((void**)&y,   g_y);
    cudaGetSymbolAddress((void**)&yv,  g_yv);

    cudaFuncSetAttribute(attn_mma_kernel,
                         cudaFuncAttributeMaxDynamicSharedMemorySize, ATTN_SMEM);

    // 1) xv_{q,k,v} = (x @ V^T) * s
    proj_rank_kernel<<<dim3(M_/64, 3), 256>>>(x, qV, kV, vV, xv);

    // 2) q,k,v = xv @ U^T
    rank_expand_kernel<<<dim3(M_/64, C_/64), 256>>>(xv,             qU, qkv);
    rank_expand_kernel<<<dim3(M_/64, C_/64), 256>>>(xv +   M_*R_,   kU, qkv + (size_t)M_*C_);
    rank_expand_kernel<<<dim3(M_/64, C_/64), 256>>>(xv + 2*M_*R_,   vU, qkv + 2*(size_t)M_*C_);

    // 3) y = causal softmax attention (tf32 tensor cores)
    attn_mma_kernel<<<dim3(T_/128, H_, B_), 256, ATTN_SMEM>>>(
        qkv, qkv + (size_t)M_*C_, qkv + 2*(size_t)M_*C_, y);

    // 4) yv = (y @ cV^T) * s ;  5) out = yv @ cU^T
    proj_rank_kernel<<<dim3(M_/64, 1), 256>>>(y, cV, cV, cV, yv);
    rank_expand_kernel<<<dim3(M_/64, C_/64), 256>>>(yv, cU, out);
}